// round 10
// baseline (speedup 1.0000x reference)
#include <cuda_runtime.h>
#include <cstdint>

// Problem constants (fixed by the dataset)
#define BATCH      16
#define NPTS       131072
#define KCENT      1024
#define NBLK       8                     // CTAs per cluster == blocks per batch
#define CHUNK      (NPTS / NBLK)         // 16384 points per block
#define THREADS    512
#define PT_PER_T   (CHUNK / THREADS)     // 32 dist values in registers per thread
#define GROUPS     (PT_PER_T / 4)        // 8 x (4 points) per thread
#define NWARP      (THREADS / 32)        // 16

typedef unsigned long long u64;

__device__ __forceinline__ uint32_t smem_u32(const void* p) {
    uint32_t a;
    asm("{ .reg .u64 t; cvta.to.shared.u64 t, %1; cvt.u32.u64 %0, t; }"
        : "=r"(a) : "l"(p));
    return a;
}

__device__ __forceinline__ uint32_t mapa_u32(uint32_t addr, uint32_t rank) {
    uint32_t r;
    asm("mapa.shared::cluster.u32 %0, %1, %2;" : "=r"(r) : "r"(addr), "r"(rank));
    return r;
}

// Packed f32x2 helpers: lane-wise .rn => bit-identical to scalar __fadd_rn/__fmul_rn.
__device__ __forceinline__ u64 f2add(u64 a, u64 b) {
    u64 r; asm("add.rn.f32x2 %0, %1, %2;" : "=l"(r) : "l"(a), "l"(b)); return r;
}
__device__ __forceinline__ u64 f2mul(u64 a, u64 b) {
    u64 r; asm("mul.rn.f32x2 %0, %1, %2;" : "=l"(r) : "l"(a), "l"(b)); return r;
}
__device__ __forceinline__ u64 f2pack(float v) {
    u64 r; asm("mov.b64 %0, {%1, %1};" : "=l"(r) : "f"(v)); return r;
}
__device__ __forceinline__ void f2unpack(float& lo, float& hi, u64 v) {
    asm("mov.b64 {%0, %1}, %2;" : "=f"(lo), "=f"(hi) : "l"(v));
}

__global__ void __launch_bounds__(THREADS, 1) __cluster_dims__(NBLK, 1, 1)
fps_kernel(const float* __restrict__ pt, float* __restrict__ out) {
    const int blk = blockIdx.x;          // 0..127
    const int b   = blk / NBLK;          // batch (== cluster id)
    const int sub = blk % NBLK;          // rank within cluster
    const int tid = threadIdx.x;
    const int wid = tid >> 5;
    const int lid = tid & 31;

    extern __shared__ float smem[];      // 3*CHUNK floats = 196608 B
    float* sx = smem;
    float* sy = smem + CHUNK;
    float* sz = smem + 2 * CHUNK;

    __shared__ u64   s_red[NWARP];
    __shared__ u64   s_slots[2][NBLK];   // parity double-buffered, written via DSMEM
    __shared__ u64   s_mbar;             // mbarrier, count=8, one phase per iter
    __shared__ float s_p[3];
    __shared__ int   s_cur;

    const float* px_g = pt + (size_t)b * 3 * NPTS;
    const float* py_g = px_g + NPTS;
    const float* pz_g = px_g + 2 * NPTS;
    const int base = sub * CHUNK;

    // ---- one-time load of this block's coordinate chunk into SMEM (vectorized)
    {
        const float4* gx = reinterpret_cast<const float4*>(px_g + base);
        const float4* gy = reinterpret_cast<const float4*>(py_g + base);
        const float4* gz = reinterpret_cast<const float4*>(pz_g + base);
        float4* lx = reinterpret_cast<float4*>(sx);
        float4* ly = reinterpret_cast<float4*>(sy);
        float4* lz = reinterpret_cast<float4*>(sz);
        for (int i = tid; i < CHUNK / 4; i += THREADS) {
            lx[i] = gx[i];
            ly[i] = gy[i];
            lz[i] = gz[i];
        }
    }

    // ---- register-resident min-distance array
    float dist[PT_PER_T];
#pragma unroll
    for (int i = 0; i < PT_PER_T; i++) dist[i] = __int_as_float(0x7f800000);  // +inf

    const uint32_t mbar_a  = smem_u32(&s_mbar);
    const uint32_t slots_a = smem_u32(&s_slots[0][0]);

    if (tid == 0) {
        s_cur  = 0;
        s_p[0] = px_g[0];
        s_p[1] = py_g[0];
        s_p[2] = pz_g[0];
        asm volatile("mbarrier.init.shared.b64 [%0], %1;"
                     :: "r"(mbar_a), "r"(NBLK) : "memory");
    }
    __syncthreads();
    // cluster-wide: all mbarriers initialized before any remote arrive
    asm volatile("barrier.cluster.arrive.aligned;" ::: "memory");
    asm volatile("barrier.cluster.wait.aligned;"   ::: "memory");

    for (int k = 0; k < KCENT; k++) {
        const int   cur = s_cur;
        const float cx = s_p[0], cy = s_p[1], cz = s_p[2];
        const int   p  = k & 1;

        // Output dtype is float32; indices < 2^24 are exact.
        if (sub == 0 && tid == 0) out[b * KCENT + k] = (float)cur;

        const u64 ncx = f2pack(-cx);
        const u64 ncy = f2pack(-cy);
        const u64 ncz = f2pack(-cz);

        // ---- update dists & local argmax with packed f32x2 math
        float best_d = -1.0f;
        int   best_i = 0;
#pragma unroll
        for (int g = 0; g < GROUPS; g++) {
            const int vi = g * THREADS + tid;
            const ulonglong2 X = reinterpret_cast<const ulonglong2*>(sx)[vi];
            const ulonglong2 Y = reinterpret_cast<const ulonglong2*>(sy)[vi];
            const ulonglong2 Z = reinterpret_cast<const ulonglong2*>(sz)[vi];
            const int p0 = base + vi * 4;

            const u64 dx0 = f2add(X.x, ncx), dx1 = f2add(X.y, ncx);
            const u64 dy0 = f2add(Y.x, ncy), dy1 = f2add(Y.y, ncy);
            const u64 dz0 = f2add(Z.x, ncz), dz1 = f2add(Z.y, ncz);
            // ((dx*dx)+(dy*dy))+(dz*dz), each step .rn — matches reference exactly
            const u64 d01 = f2add(f2add(f2mul(dx0, dx0), f2mul(dy0, dy0)),
                                  f2mul(dz0, dz0));
            const u64 d23 = f2add(f2add(f2mul(dx1, dx1), f2mul(dy1, dy1)),
                                  f2mul(dz1, dz1));
            float dv[4];
            f2unpack(dv[0], dv[1], d01);
            f2unpack(dv[2], dv[3], d23);
#pragma unroll
            for (int j = 0; j < 4; j++) {
                const float nd = fminf(dist[g * 4 + j], dv[j]);
                dist[g * 4 + j] = nd;
                if (nd > best_d) { best_d = nd; best_i = p0 + j; }
            }
        }

        // ---- pack (dist, ~idx): max over packed == max dist, ties -> lowest idx.
        u64 key = ((u64)__float_as_uint(best_d) << 32) |
                  (unsigned)(~(unsigned)best_i);

        // warp reduce
#pragma unroll
        for (int off = 16; off > 0; off >>= 1) {
            u64 o = __shfl_down_sync(0xffffffffu, key, off);
            if (o > key) key = o;
        }
        if (lid == 0) s_red[wid] = key;
        __syncthreads();

        // ---- warp 0 only: cross-CTA exchange via DSMEM + mbarrier
        if (wid == 0) {
            u64 v = (lid < NWARP) ? s_red[lid] : 0ull;
#pragma unroll
            for (int off = 8; off > 0; off >>= 1) {
                u64 o = __shfl_down_sync(0xffffffffu, v, off);
                if (o > v) v = o;
            }
            const u64 bb = __shfl_sync(0xffffffffu, v, 0);

            if (lid < NBLK) {
                // write this CTA's partial into peer rank 'lid', then release-arrive
                const uint32_t slot_l = slots_a + (uint32_t)(p * NBLK + sub) * 8u;
                const uint32_t slot_r = mapa_u32(slot_l, (uint32_t)lid);
                asm volatile("st.shared::cluster.u64 [%0], %1;"
                             :: "r"(slot_r), "l"(bb) : "memory");
                const uint32_t mbar_r = mapa_u32(mbar_a, (uint32_t)lid);
                asm volatile("mbarrier.arrive.release.cluster.shared::cluster.b64 _, [%0];"
                             :: "r"(mbar_r) : "memory");
            }

            // bounded wait on local mbarrier for all 8 arrivals of this phase
            {
                uint32_t done = 0;
                for (int t = 0; t < (1 << 22) && !done; ++t) {
                    asm volatile(
                        "{ .reg .pred q;\n\t"
                        "mbarrier.try_wait.parity.acquire.cluster.shared::cta.b64 q, [%1], %2, 0x989680;\n\t"
                        "selp.b32 %0, 1, 0, q; }"
                        : "=r"(done) : "r"(mbar_a), "r"((uint32_t)p) : "memory");
                }
            }

            // reduce the 8 slots (now local in SMEM)
            u64 w = (lid < NBLK) ? s_slots[p][lid] : 0ull;
#pragma unroll
            for (int off = 4; off > 0; off >>= 1) {
                u64 o = __shfl_down_sync(0xffffffffu, w, off);
                if (o > w) w = o;
            }
            const int nxt = (int)(~(unsigned)(__shfl_sync(0xffffffffu, w, 0) & 0xffffffffu));
            if (lid == 0) s_cur = nxt;
            if (lid < 3)  s_p[lid] = px_g[(size_t)lid * NPTS + nxt];  // 3 parallel L2 loads
        }
        __syncthreads();
    }
}

extern "C" void kernel_launch(void* const* d_in, const int* in_sizes, int n_in,
                              void* d_out, int out_size) {
    // Select the coordinate buffer by SIZE, not position: pt has 6291456 elements.
    const float* ptc = nullptr;
    for (int i = 0; i < n_in; i++) {
        if (in_sizes[i] == BATCH * 3 * NPTS) { ptc = (const float*)d_in[i]; break; }
    }
    if (!ptc) {  // fallback: largest input
        int bi = 0;
        for (int i = 1; i < n_in; i++) if (in_sizes[i] > in_sizes[bi]) bi = i;
        ptc = (const float*)d_in[bi];
    }
    float* out = (float*)d_out;
    (void)out_size;

    const int smem_bytes = 3 * CHUNK * sizeof(float);  // 196608 B
    cudaFuncSetAttribute(fps_kernel,
                         cudaFuncAttributeMaxDynamicSharedMemorySize,
                         smem_bytes);

    fps_kernel<<<BATCH * NBLK, THREADS, smem_bytes>>>(ptc, out);
}

// round 11
// speedup vs baseline: 1.1580x; 1.1580x over previous
#include <cuda_runtime.h>
#include <cstdint>

// Problem constants (fixed by the dataset)
#define BATCH      16
#define NPTS       131072
#define KCENT      1024
#define NBLK       8                    // blocks cooperating per batch
#define CHUNK      (NPTS / NBLK)        // 16384 points per block
#define THREADS    512
#define PT_PER_T   (CHUNK / THREADS)    // 32 dist values in registers per thread
#define GROUPS     (PT_PER_T / 4)       // 8 float4 groups per thread
#define NWARP      (THREADS / 32)       // 16

typedef unsigned long long u64;

// Cross-block communication (device globals: no allocation allowed)
__device__ u64      g_key[BATCH][2][NBLK];   // packed (dist,~idx) partials, parity-buffered
__device__ float4   g_xyz[BATCH][2][NBLK];   // candidate coordinates, parity-buffered
__device__ unsigned g_cnt[BATCH];            // monotonic barrier counters

__global__ void fps_init_kernel() {
    if (threadIdx.x < BATCH) g_cnt[threadIdx.x] = 0u;
}

// R8-proven design: coordinates read from global every iteration; each block's
// 196 KB chunk is L1D-resident (228 KB L1, no cluster.sync => no per-iter flush).
__global__ void __launch_bounds__(THREADS, 1)
fps_kernel(const float* __restrict__ pt, float* __restrict__ out) {
    const int blk = blockIdx.x;        // 0..127
    const int b   = blk / NBLK;        // batch
    const int sub = blk % NBLK;        // sub-block within batch
    const int tid = threadIdx.x;
    const int wid = tid >> 5;
    const int lid = tid & 31;

    __shared__ u64   s_red[NWARP];
    __shared__ float s_p[3];
    __shared__ int   s_cur;

    const float* px_g = pt + (size_t)b * 3 * NPTS;
    const float* py_g = px_g + NPTS;
    const float* pz_g = px_g + 2 * NPTS;
    const int base = sub * CHUNK;

    const float4* __restrict__ gx = reinterpret_cast<const float4*>(px_g + base);
    const float4* __restrict__ gy = reinterpret_cast<const float4*>(py_g + base);
    const float4* __restrict__ gz = reinterpret_cast<const float4*>(pz_g + base);

    // ---- register-resident min-distance array
    float dist[PT_PER_T];
#pragma unroll
    for (int i = 0; i < PT_PER_T; i++) dist[i] = __int_as_float(0x7f800000);  // +inf

    if (tid == 0) {
        s_cur  = 0;
        s_p[0] = px_g[0];
        s_p[1] = py_g[0];
        s_p[2] = pz_g[0];
    }
    __syncthreads();

    for (int k = 0; k < KCENT; k++) {
        const int   cur = s_cur;
        const float cx = s_p[0], cy = s_p[1], cz = s_p[2];
        const int   p  = k & 1;

        // Output dtype is float32; indices < 2^24 are exact.
        if (sub == 0 && tid == 0) out[b * KCENT + k] = (float)cur;

        // ---- update dists & local argmax (R8-identical scalar math, rel_err 0.0)
        float best_d = -1.0f;
        int   best_i = 0;
#pragma unroll
        for (int g = 0; g < GROUPS; g++) {
            const int vi = g * THREADS + tid;
            const float4 x4 = gx[vi];
            const float4 y4 = gy[vi];
            const float4 z4 = gz[vi];
            const int p0 = base + vi * 4;
            const float xs[4] = {x4.x, x4.y, x4.z, x4.w};
            const float ys[4] = {y4.x, y4.y, y4.z, y4.w};
            const float zs[4] = {z4.x, z4.y, z4.z, z4.w};
#pragma unroll
            for (int j = 0; j < 4; j++) {
                const float dx = __fadd_rn(xs[j], -cx);
                const float dy = __fadd_rn(ys[j], -cy);
                const float dz = __fadd_rn(zs[j], -cz);
                const float d  = __fadd_rn(__fadd_rn(__fmul_rn(dx, dx),
                                                     __fmul_rn(dy, dy)),
                                           __fmul_rn(dz, dz));
                const float nd = fminf(dist[g * 4 + j], d);
                dist[g * 4 + j] = nd;
                if (nd > best_d) { best_d = nd; best_i = p0 + j; }
            }
        }

        // ---- pack (dist, ~idx): max over packed == max dist, ties -> lowest idx.
        u64 key = ((u64)__float_as_uint(best_d) << 32) |
                  (unsigned)(~(unsigned)best_i);

        // warp reduce
#pragma unroll
        for (int off = 16; off > 0; off >>= 1) {
            u64 o = __shfl_down_sync(0xffffffffu, key, off);
            if (o > key) key = o;
        }
        if (lid == 0) s_red[wid] = key;
        __syncthreads();

        // ---- warp 0: block reduce + warp-parallel cross-CTA exchange via L2
        if (wid == 0) {
            u64 v = (lid < NWARP) ? s_red[lid] : 0ull;
#pragma unroll
            for (int off = 8; off > 0; off >>= 1) {
                u64 o = __shfl_down_sync(0xffffffffu, v, off);
                if (o > v) v = o;
            }
            const u64 bb = __shfl_sync(0xffffffffu, v, 0);

            if (lid == 0) {
                // this CTA's candidate coords: L1-hit (index in own chunk)
                const int bi = (int)(~(unsigned)(bb & 0xffffffffu));
                float4 c;
                c.x = px_g[bi]; c.y = py_g[bi]; c.z = pz_g[bi]; c.w = 0.0f;
                g_key[b][p][sub] = bb;
                g_xyz[b][p][sub] = c;
                // release-arrive: orders the two stores above, no separate membar
                unsigned old;
                asm volatile("atom.add.release.gpu.u32 %0, [%1], %2;"
                             : "=r"(old) : "l"(&g_cnt[b]), "r"(1u) : "memory");
            }

            // all 32 lanes poll the same address (broadcast load, one request).
            // Tight acquire loop; L2 round-trip is the natural backoff. Bounded.
            const unsigned target = (unsigned)(NBLK * (k + 1));
            unsigned cnt = 0;
            int t = 0;
            do {
                asm volatile("ld.acquire.gpu.u32 %0, [%1];"
                             : "=r"(cnt) : "l"(&g_cnt[b]) : "memory");
            } while (cnt < target && ++t < (1 << 18));

            // lanes 0..7 load the 8 slots in parallel (MLP=8)
            u64    kj = 0ull;
            float4 cj = make_float4(0.f, 0.f, 0.f, 0.f);
            if (lid < NBLK) {
                kj = g_key[b][p][lid];
                cj = g_xyz[b][p][lid];
            }
            u64 m = kj;
#pragma unroll
            for (int off = 4; off > 0; off >>= 1) {   // xor-reduce within lanes 0..7
                u64 o = __shfl_xor_sync(0xffffffffu, m, off);
                if (o > m) m = o;
            }
            // keys are unique (distinct indices): exactly one lane matches
            if (lid < NBLK && kj == m) {
                s_cur  = (int)(~(unsigned)(m & 0xffffffffu));
                s_p[0] = cj.x;
                s_p[1] = cj.y;
                s_p[2] = cj.z;
            }
        }
        __syncthreads();
    }
}

extern "C" void kernel_launch(void* const* d_in, const int* in_sizes, int n_in,
                              void* d_out, int out_size) {
    // Select the coordinate buffer by SIZE, not position: pt has 6291456 elements.
    const float* ptc = nullptr;
    for (int i = 0; i < n_in; i++) {
        if (in_sizes[i] == BATCH * 3 * NPTS) { ptc = (const float*)d_in[i]; break; }
    }
    if (!ptc) {  // fallback: largest input
        int bi = 0;
        for (int i = 1; i < n_in; i++) if (in_sizes[i] > in_sizes[bi]) bi = i;
        ptc = (const float*)d_in[bi];
    }
    float* out = (float*)d_out;
    (void)out_size;

    fps_init_kernel<<<1, 32>>>();
    fps_kernel<<<BATCH * NBLK, THREADS>>>(ptc, out);
}

// round 12
// speedup vs baseline: 1.2933x; 1.1168x over previous
#include <cuda_runtime.h>
#include <cstdint>

// Problem constants (fixed by the dataset)
#define BATCH      16
#define NPTS       131072
#define KCENT      1024
#define NBLK       8                    // blocks cooperating per batch
#define CHUNK      (NPTS / NBLK)        // 16384 points per block
#define THREADS    1024
#define PT_PER_T   (CHUNK / THREADS)    // 16 dist values in registers per thread
#define GROUPS     (PT_PER_T / 4)       // 4 float4 groups per thread
#define NWARP      (THREADS / 32)       // 32

typedef unsigned long long u64;

// Cross-CTA exchange: 4 self-verifying words per CTA, parity double-buffered.
//   word0 = [distbits:32 | (idx^0x1FFFF):17 | seq:15]
//   word1..3 = [float bits of x/y/z : 32 | seq:32]
// seq = k+1 (1..1024). A word is valid iff its seq field matches the target,
// so no atomics, fences, or counters are needed; stale cross-replay values
// can never alias a fresh seq (slot for parity p at iter k last held seq k-1).
__device__ u64 g_slot[BATCH][2][NBLK][4];

__global__ void __launch_bounds__(THREADS, 1)
fps_kernel(const float* __restrict__ pt, float* __restrict__ out) {
    const int blk = blockIdx.x;        // 0..127
    const int b   = blk / NBLK;        // batch
    const int sub = blk % NBLK;        // sub-block within batch
    const int tid = threadIdx.x;
    const int wid = tid >> 5;
    const int lid = tid & 31;

    __shared__ u64   s_red[NWARP];
    __shared__ float s_p[3];
    __shared__ int   s_cur;

    const float* px_g = pt + (size_t)b * 3 * NPTS;
    const float* py_g = px_g + NPTS;
    const float* pz_g = px_g + 2 * NPTS;
    const int base = sub * CHUNK;

    const float4* __restrict__ gx = reinterpret_cast<const float4*>(px_g + base);
    const float4* __restrict__ gy = reinterpret_cast<const float4*>(py_g + base);
    const float4* __restrict__ gz = reinterpret_cast<const float4*>(pz_g + base);

    // ---- register-resident min-distance array
    float dist[PT_PER_T];
#pragma unroll
    for (int i = 0; i < PT_PER_T; i++) dist[i] = __int_as_float(0x7f800000);  // +inf

    if (tid == 0) {
        s_cur  = 0;
        s_p[0] = px_g[0];
        s_p[1] = py_g[0];
        s_p[2] = pz_g[0];
    }
    __syncthreads();

    for (int k = 0; k < KCENT; k++) {
        const int   cur = s_cur;
        const float cx = s_p[0], cy = s_p[1], cz = s_p[2];
        const int   p  = k & 1;

        // Output dtype is float32; indices < 2^24 are exact.
        if (sub == 0 && tid == 0) out[b * KCENT + k] = (float)cur;

        // ---- update dists & local argmax (bit-exact scalar math, rel_err 0.0)
        float best_d = -1.0f;
        int   best_i = 0;
#pragma unroll
        for (int g = 0; g < GROUPS; g++) {
            const int vi = g * THREADS + tid;
            const float4 x4 = gx[vi];
            const float4 y4 = gy[vi];
            const float4 z4 = gz[vi];
            const int p0 = base + vi * 4;
            const float xs[4] = {x4.x, x4.y, x4.z, x4.w};
            const float ys[4] = {y4.x, y4.y, y4.z, y4.w};
            const float zs[4] = {z4.x, z4.y, z4.z, z4.w};
#pragma unroll
            for (int j = 0; j < 4; j++) {
                const float dx = __fadd_rn(xs[j], -cx);
                const float dy = __fadd_rn(ys[j], -cy);
                const float dz = __fadd_rn(zs[j], -cz);
                const float d  = __fadd_rn(__fadd_rn(__fmul_rn(dx, dx),
                                                     __fmul_rn(dy, dy)),
                                           __fmul_rn(dz, dz));
                const float nd = fminf(dist[g * 4 + j], d);
                dist[g * 4 + j] = nd;
                if (nd > best_d) { best_d = nd; best_i = p0 + j; }
            }
        }

        // ---- pack (dist, ~idx): max over packed == max dist, ties -> lowest idx.
        u64 key = ((u64)__float_as_uint(best_d) << 32) |
                  (unsigned)(~(unsigned)best_i);

        // warp reduce
#pragma unroll
        for (int off = 16; off > 0; off >>= 1) {
            u64 o = __shfl_down_sync(0xffffffffu, key, off);
            if (o > key) key = o;
        }
        if (lid == 0) s_red[wid] = key;
        __syncthreads();

        // ---- warp 0: block reduce + one-round-trip cross-CTA exchange
        if (wid == 0) {
            u64 v = s_red[lid];                        // NWARP == 32
#pragma unroll
            for (int off = 16; off > 0; off >>= 1) {
                u64 o = __shfl_down_sync(0xffffffffu, v, off);
                if (o > v) v = o;
            }
            const u64 bb = __shfl_sync(0xffffffffu, v, 0);
            const unsigned seq = (unsigned)(k + 1);

            // lanes 0..3 publish this CTA's 4 words (coords are L1 hits: own chunk)
            if (lid < 4) {
                u64 w;
                if (lid == 0) {
                    const unsigned distb = (unsigned)(bb >> 32);
                    const unsigned idx   = ~(unsigned)bb;           // 17 bits
                    w = ((u64)distb << 32) |
                        ((u64)((idx ^ 0x1FFFFu) & 0x1FFFFu) << 15) | seq;
                } else {
                    const int bi = (int)(~(unsigned)bb);
                    const float c = px_g[(size_t)(lid - 1) * NPTS + bi];
                    w = ((u64)__float_as_uint(c) << 32) | seq;
                }
                asm volatile("st.relaxed.gpu.u64 [%0], %1;"
                             :: "l"(&g_slot[b][p][sub][lid]), "l"(w) : "memory");
            }

            // all 32 lanes poll: lane l owns word (l&3) of CTA (l>>2)
            const int rr = lid >> 2, ww = lid & 3;
            const u64* addr = &g_slot[b][p][rr][ww];
            u64 wv = 0;
            int t = 0;
            for (;;) {
                asm volatile("ld.relaxed.gpu.u64 %0, [%1];"
                             : "=l"(wv) : "l"(addr) : "memory");
                const unsigned got = (ww == 0) ? (unsigned)(wv & 0x7FFFu)
                                               : (unsigned)wv;
                if (got == seq || ++t >= (1 << 20)) break;
            }

            // global max over the 8 key words (lanes 0,4,...,28); others contribute 0
            u64 m = (ww == 0) ? wv : 0ull;
#pragma unroll
            for (int off = 4; off <= 16; off <<= 1) {
                u64 o = __shfl_xor_sync(0xffffffffu, m, off);
                if (o > m) m = o;
            }
            const u64 gk = __shfl_sync(0xffffffffu, m, 0);

            // winner CTA: exactly one key lane matches (indices unique)
            const unsigned mk  = __ballot_sync(0xffffffffu, (ww == 0) && (wv == gk));
            const int      src = __ffs(mk) - 1;                    // = 4 * winner_rank
            const float xx = __uint_as_float((unsigned)(__shfl_sync(0xffffffffu, wv, src + 1) >> 32));
            const float yy = __uint_as_float((unsigned)(__shfl_sync(0xffffffffu, wv, src + 2) >> 32));
            const float zz = __uint_as_float((unsigned)(__shfl_sync(0xffffffffu, wv, src + 3) >> 32));
            const int nxt = (int)((((unsigned)(gk >> 15)) & 0x1FFFFu) ^ 0x1FFFFu);

            if (lid == 0) {
                s_cur  = nxt;
                s_p[0] = xx;
                s_p[1] = yy;
                s_p[2] = zz;
            }
        }
        __syncthreads();
    }
}

extern "C" void kernel_launch(void* const* d_in, const int* in_sizes, int n_in,
                              void* d_out, int out_size) {
    // Select the coordinate buffer by SIZE, not position: pt has 6291456 elements.
    const float* ptc = nullptr;
    for (int i = 0; i < n_in; i++) {
        if (in_sizes[i] == BATCH * 3 * NPTS) { ptc = (const float*)d_in[i]; break; }
    }
    if (!ptc) {  // fallback: largest input
        int bi = 0;
        for (int i = 1; i < n_in; i++) if (in_sizes[i] > in_sizes[bi]) bi = i;
        ptc = (const float*)d_in[bi];
    }
    float* out = (float*)d_out;
    (void)out_size;

    fps_kernel<<<BATCH * NBLK, THREADS>>>(ptc, out);
}